// round 6
// baseline (speedup 1.0000x reference)
#include <cuda_runtime.h>
#include <cuda_bf16.h>

// ChamferLoss via exact pruned nearest-neighbor search.
// 1) Morton counting-sort both sets (16^3 grid, 12-bit codes).
// 2) Per-32-point-group bounding spheres.
// 3) Per-point sweep over groups with conservative triangle-inequality pruning:
//    prune group iff |x - c|^2 > (ub + r)^2, ub = sqrt(current best d2).
//    A group containing the true NN can never be pruned -> exact mins,
//    deterministic output regardless of scatter order.

#define NPTS   16384
#define NBINS  4096           // 12-bit morton (4 bits/axis)
#define NGRP   (NPTS / 32)    // 512 groups per set
#define BT     128
#define NZERO  (2 * NPTS > 2 * NBINS ? 2 * NPTS : 2 * NBINS)

#define INFF __int_as_float(0x7f800000)

__device__ float4       g_sorted[2][NPTS];   // {x,y,z, 0.5*|p|^2}
__device__ int          g_orig[2][NPTS];
__device__ unsigned     g_code[2][NPTS];
__device__ unsigned     g_hist[2][NBINS];
__device__ unsigned     g_off[2][NBINS];
__device__ unsigned     g_tick[2][NBINS];
__device__ float4       g_bounds[2][NGRP];   // {cx,cy,cz, r}
__device__ unsigned     g_minbits[2 * NPTS];

// ---------- K0: zero hist/tick/minbits ----------
__global__ void k_zero() {
    int i = blockIdx.x * blockDim.x + threadIdx.x;
    if (i < 2 * NBINS) { (&g_hist[0][0])[i] = 0; (&g_tick[0][0])[i] = 0; }
    if (i < 2 * NPTS)  g_minbits[i] = 0x7f800000u;
}

__device__ __forceinline__ unsigned spread4(unsigned v) {
    return (v & 1u) | ((v & 2u) << 2) | ((v & 4u) << 4) | ((v & 8u) << 6);
}
__device__ __forceinline__ unsigned morton(float x, float y, float z) {
    int qx = (int)((x + 5.0f) * 1.6f); qx = max(0, min(15, qx));
    int qy = (int)((y + 5.0f) * 1.6f); qy = max(0, min(15, qy));
    int qz = (int)((z + 5.0f) * 1.6f); qz = max(0, min(15, qz));
    return spread4((unsigned)qx) | (spread4((unsigned)qy) << 1) | (spread4((unsigned)qz) << 2);
}

// ---------- K1: codes + histogram ----------
__global__ void k_code(const float* __restrict__ pred, const float* __restrict__ gt) {
    int i = blockIdx.x * blockDim.x + threadIdx.x;
    if (i >= 2 * NPTS) return;
    int s = i >> 14, p = i & (NPTS - 1);
    const float* src = s ? gt : pred;
    unsigned c = morton(src[3 * p], src[3 * p + 1], src[3 * p + 2]);
    g_code[s][p] = c;
    atomicAdd(&g_hist[s][c], 1u);
}

// ---------- K2: exclusive scan of both histograms (1 block, 4 bins/thread) ----------
__global__ __launch_bounds__(1024) void k_scan() {
    __shared__ unsigned part[1024];
    const int t = threadIdx.x;
    for (int s = 0; s < 2; ++s) {
        const int base = t * 4;
        unsigned h0 = g_hist[s][base + 0];
        unsigned h1 = g_hist[s][base + 1];
        unsigned h2 = g_hist[s][base + 2];
        unsigned h3 = g_hist[s][base + 3];
        part[t] = h0 + h1 + h2 + h3;
        __syncthreads();
        for (int d = 1; d < 1024; d <<= 1) {
            unsigned v = (t >= d) ? part[t - d] : 0u;
            __syncthreads();
            part[t] += v;
            __syncthreads();
        }
        unsigned excl = (t == 0) ? 0u : part[t - 1];
        g_off[s][base + 0] = excl;
        g_off[s][base + 1] = excl + h0;
        g_off[s][base + 2] = excl + h0 + h1;
        g_off[s][base + 3] = excl + h0 + h1 + h2;
        __syncthreads();
    }
}

// ---------- K3: scatter into sorted order ----------
__global__ void k_scatter(const float* __restrict__ pred, const float* __restrict__ gt) {
    int i = blockIdx.x * blockDim.x + threadIdx.x;
    if (i >= 2 * NPTS) return;
    int s = i >> 14, p = i & (NPTS - 1);
    const float* src = s ? gt : pred;
    float x = src[3 * p], y = src[3 * p + 1], z = src[3 * p + 2];
    unsigned c = g_code[s][p];
    unsigned pos = g_off[s][c] + atomicAdd(&g_tick[s][c], 1u);
    g_sorted[s][pos] = make_float4(x, y, z, 0.5f * (x * x + y * y + z * z));
    g_orig[s][pos] = p;
}

// ---------- K4: group bounding spheres (1 warp per group) ----------
__global__ void k_bounds() {
    int gid = (blockIdx.x * blockDim.x + threadIdx.x) >> 5;
    int lane = threadIdx.x & 31;
    if (gid >= 2 * NGRP) return;
    int s = gid >= NGRP, g = gid & (NGRP - 1);
    float4 pv = g_sorted[s][g * 32 + lane];
    float sx = pv.x, sy = pv.y, sz = pv.z;
#pragma unroll
    for (int d = 16; d > 0; d >>= 1) {
        sx += __shfl_xor_sync(0xffffffffu, sx, d);
        sy += __shfl_xor_sync(0xffffffffu, sy, d);
        sz += __shfl_xor_sync(0xffffffffu, sz, d);
    }
    float cx = sx * (1.0f / 32.0f), cy = sy * (1.0f / 32.0f), cz = sz * (1.0f / 32.0f);
    float dx = pv.x - cx, dy = pv.y - cy, dz = pv.z - cz;
    float r2 = dx * dx + dy * dy + dz * dz;
#pragma unroll
    for (int d = 16; d > 0; d >>= 1)
        r2 = fmaxf(r2, __shfl_xor_sync(0xffffffffu, r2, d));
    if (lane == 0)
        g_bounds[s][g] = make_float4(cx, cy, cz, sqrtf(r2));
}

// ---------- K5: pruned min sweep ----------
__global__ __launch_bounds__(BT) void k_main() {
    const int dir = blockIdx.z;       // x = set[dir], y = set[dir^1]
    const int sx = dir, sy = dir ^ 1;

    __shared__ float4 sb[NGRP];       // y-group bounds
    __shared__ float4 stage[BT];      // per-warp y staging (32 slots per warp)

    for (int i = threadIdx.x; i < NGRP; i += BT) sb[i] = g_bounds[sy][i];
    __syncthreads();

    const int p = blockIdx.x * BT + threadIdx.x;
    const float4 xp = g_sorted[sx][p];
    const int orig = g_orig[sx][p];
    const float x2 = 2.0f * xp.w;     // |x|^2
    const int lane = threadIdx.x & 31;
    const int wbase = threadIdx.x & ~31;
    const int g0 = (blockIdx.x * BT + wbase) >> 5;   // warp-uniform start group

    float m = INFF;     // min over evaluated y of (0.5|y|^2 - x.y)
    float ub = INFF;    // sqrt of current best d2 (conservative upper bound)

    // Sweep forward from g0, then backward from g0-1 (near groups first).
    for (int pass = 0; pass < 2; ++pass) {
        int gbeg = pass == 0 ? g0 : g0 - 1;
        int gend = pass == 0 ? NGRP : -1;
        int gstep = pass == 0 ? 1 : -1;
        for (int g = gbeg; g != gend; g += gstep) {
            float4 b = sb[g];
            float d0 = xp.x - b.x, d1 = xp.y - b.y, d2c = xp.z - b.z;
            float dc2 = fmaf(d0, d0, fmaf(d1, d1, d2c * d2c));
            float thr = ub + b.w;
            bool need = !(dc2 > thr * thr);
            if (__any_sync(0xffffffffu, need)) {
                stage[threadIdx.x] = g_sorted[sy][g * 32 + lane];
                __syncwarp();
                float mold = m;
                float m0 = m, m1 = INFF;
#pragma unroll
                for (int i2 = 0; i2 < 32; i2 += 2) {
                    float4 ya = stage[wbase + i2];
                    float4 yb = stage[wbase + i2 + 1];
                    float ta = fmaf(-xp.x, ya.x, ya.w);
                    ta = fmaf(-xp.y, ya.y, ta);
                    ta = fmaf(-xp.z, ya.z, ta);
                    m0 = fminf(m0, ta);
                    float tb = fmaf(-xp.x, yb.x, yb.w);
                    tb = fmaf(-xp.y, yb.y, tb);
                    tb = fmaf(-xp.z, yb.z, tb);
                    m1 = fminf(m1, tb);
                }
                m = fminf(m0, m1);
                __syncwarp();
                if (__any_sync(0xffffffffu, m < mold))
                    ub = sqrtf(fmaxf(fmaf(2.0f, m, x2), 0.0f));
            }
        }
    }

    float d2 = fmaxf(fmaf(2.0f, m, x2), 0.0f);
    atomicMin(&g_minbits[dir * NPTS + orig], __float_as_uint(d2));
}

// ---------- K6: final reduce ----------
__global__ __launch_bounds__(1024) void k_reduce(float* __restrict__ out) {
    __shared__ float red[1024];
    float s = 0.0f;
    for (int i = threadIdx.x; i < 2 * NPTS; i += 1024)
        s += sqrtf(__uint_as_float(g_minbits[i]));
    red[threadIdx.x] = s;
    __syncthreads();
    for (int w = 512; w > 0; w >>= 1) {
        if (threadIdx.x < w) red[threadIdx.x] += red[threadIdx.x + w];
        __syncthreads();
    }
    if (threadIdx.x == 0) out[0] = red[0] * (1.0f / (float)NPTS);
}

extern "C" void kernel_launch(void* const* d_in, const int* in_sizes, int n_in,
                              void* d_out, int out_size) {
    const float* pred = (const float*)d_in[0];
    const float* gt   = (const float*)d_in[1];
    float* out = (float*)d_out;

    k_zero<<<(NZERO + 255) / 256, 256>>>();           // FIX: cover all of g_minbits
    k_code<<<(2 * NPTS + 255) / 256, 256>>>(pred, gt);
    k_scan<<<1, 1024>>>();
    k_scatter<<<(2 * NPTS + 255) / 256, 256>>>(pred, gt);
    k_bounds<<<(2 * NGRP * 32 + 255) / 256, 256>>>();
    dim3 grid(NPTS / BT, 1, 2);
    k_main<<<grid, BT>>>();
    k_reduce<<<1, 1024>>>(out);
}